// round 1
// baseline (speedup 1.0000x reference)
#include <cuda_runtime.h>

// CosRec fused kernel — fp32 SIMT baseline, one CTA per batch row.
//
// Sizes (fixed by the problem): BATCH=512, SEQ_LEN=32, EMBED_DIM=64,
// FC_DIM=100, T=3. Dominant work: per-batch GEMM (1024 x 100) @ (100 x 100).

#define THREADS 256
// XOR swizzle on the g index of the transposed Wf2 tile (granularity 4 floats
// keeps float4 alignment); cuts the one-time transpose write conflicts.
#define SWZ(g, f) ((g) ^ (((f) & 7) << 2))

// Shared layout (floats):
//   sWt   [100][128]  Wf2 transposed (f-major, g padded/zeroed to 128)  12800
//   sAf   [100][32]   A + b1, f-major                                    3200
//   sBf   [100][32]   Bm, f-major                                        3200
//   slotU [6400]      union: W1 k-chunk (100x64) / h1 tile (100x64)      6400
//   slotE [2112]      union: E^T (64x33 padded) / xacc reduction (16x128) 2112
//   sbf2  [128]       bf2 padded with zeros                               128
//   sX    [164]       final feature vector [x(100) | uemb(64)]            164
//   sI    [36] ints   32 seq idx, 3 item idx, 1 user idx
static const int SMEM_FLOATS = 12800 + 3200 + 3200 + 6400 + 2112 + 128 + 164;
static const size_t SMEM_BYTES = (size_t)SMEM_FLOATS * 4 + 36 * 4;

__global__ __launch_bounds__(THREADS)
void cosrec_kernel(
    const int*   __restrict__ seq_var,   // [512*32]
    const int*   __restrict__ user_var,  // [512]
    const int*   __restrict__ item_var,  // [512*3]
    const float* __restrict__ item_emb,  // [100000*64]
    const float* __restrict__ user_emb,  // [100000*64]
    const float* __restrict__ W2,        // [100000*164]
    const float* __restrict__ b2,        // [100000]
    const float* __restrict__ W1,        // [100*128]
    const float* __restrict__ b1,        // [100]
    const float* __restrict__ Wf2,       // [100*100]
    const float* __restrict__ bf2,       // [100]
    float*       __restrict__ out)       // [512*3]
{
    extern __shared__ float smem[];
    float* sWt   = smem;              // 12800
    float* sAf   = sWt + 12800;       // 3200
    float* sBf   = sAf + 3200;        // 3200
    float* slotU = sBf + 3200;        // 6400
    float* slotE = slotU + 6400;      // 2112
    float* sbf2  = slotE + 2112;      // 128
    float* sX    = sbf2 + 128;        // 164
    int*   sI    = (int*)(sX + 164);  // 36 ints

    const int b   = blockIdx.x;
    const int tid = threadIdx.x;

    // ---- indices + small vectors ----
    if (tid < 32)                 sI[tid] = seq_var[b * 32 + tid];
    else if (tid < 35)            sI[tid] = item_var[b * 3 + (tid - 32)];
    else if (tid == 35)           sI[35]  = user_var[b];
    if (tid < 128)                sbf2[tid] = (tid < 100) ? bf2[tid] : 0.0f;
    for (int i = tid; i < 12800; i += THREADS) sWt[i] = 0.0f;  // zero incl. g-pad
    __syncthreads();

    // ---- gather embeddings: sEt[d*33 + l] (transposed, padded stride) ----
    float* sEt = slotE;
    for (int idx = tid; idx < 2048; idx += THREADS) {
        int l = idx >> 6, d = idx & 63;
        sEt[d * 33 + l] = item_emb[(size_t)sI[l] * 64 + d];
    }
    // ---- Wf2 -> transposed + swizzled shared tile ----
    for (int idx = tid; idx < 10000; idx += THREADS) {
        int g = idx / 100, f = idx - g * 100;
        sWt[f * 128 + SWZ(g, f)] = Wf2[idx];
    }
    __syncthreads();

    // ---- A = E@Wa^T + b1, Bm = E@Wb^T  (W1 staged in two 32-wide k-chunks) ----
    float* sW1c = slotU;  // [100][64]: cols 0..31 = Wa chunk, 32..63 = Wb chunk
    for (int c = 0; c < 2; ++c) {
        for (int idx = tid; idx < 6400; idx += THREADS) {
            int f = idx >> 6, jj = idx & 63;
            int half = jj >> 5, j = jj & 31;
            sW1c[idx] = W1[f * 128 + half * 64 + c * 32 + j];
        }
        __syncthreads();
        for (int idx = tid; idx < 3200; idx += THREADS) {
            int f = idx >> 5, l = idx & 31;
            float accA = 0.0f, accB = 0.0f;
            #pragma unroll
            for (int j = 0; j < 32; ++j) {
                float e = sEt[(c * 32 + j) * 33 + l];
                accA = fmaf(e, sW1c[f * 64 + j],      accA);
                accB = fmaf(e, sW1c[f * 64 + 32 + j], accB);
            }
            if (c == 0) { sAf[idx] = accA;                sBf[idx] = accB; }
            else        { sAf[idx] += accA + b1[f];       sBf[idx] += accB; }
        }
        __syncthreads();
    }

    // ---- main GEMM: 16 tiles of 64 pairs, thread tile 4(pairs) x 8(g) ----
    const int tm = tid >> 4;   // 0..15 (4 pairs each)
    const int tn = tid & 15;   // 0..15 (8 g each)
    float xacc[8];
    #pragma unroll
    for (int u = 0; u < 8; ++u) xacc[u] = 0.0f;

    float* sHt = slotU;  // [100][64], f-major h1 tile (reuses W1 chunk slot)

    for (int mt = 0; mt < 16; ++mt) {
        __syncthreads();  // previous tile consumed / slot handoff
        for (int idx = tid; idx < 6400; idx += THREADS) {
            int f = idx >> 6, i = idx & 63;
            int p = mt * 64 + i;
            float v = sAf[f * 32 + (p & 31)] + sBf[f * 32 + (p >> 5)];
            sHt[idx] = fmaxf(v, 0.0f);
        }
        __syncthreads();

        float acc[4][8];
        #pragma unroll
        for (int i = 0; i < 4; ++i)
            #pragma unroll
            for (int u = 0; u < 8; ++u) acc[i][u] = 0.0f;

        const float* hp = sHt + tm * 4;
        #pragma unroll 4
        for (int f = 0; f < 100; ++f) {
            float4 av  = *(const float4*)(hp + f * 64);
            const float* wp = sWt + f * 128;
            float4 bv0 = *(const float4*)(wp + SWZ(tn * 8,     f));
            float4 bv1 = *(const float4*)(wp + SWZ(tn * 8 + 4, f));
            float aa[4] = {av.x, av.y, av.z, av.w};
            float bb[8] = {bv0.x, bv0.y, bv0.z, bv0.w,
                           bv1.x, bv1.y, bv1.z, bv1.w};
            #pragma unroll
            for (int i = 0; i < 4; ++i)
                #pragma unroll
                for (int u = 0; u < 8; ++u)
                    acc[i][u] = fmaf(aa[i], bb[u], acc[i][u]);
        }
        // bias + relu + accumulate into per-thread x (g-pad contributes 0)
        #pragma unroll
        for (int u = 0; u < 8; ++u) {
            float bias = sbf2[tn * 8 + u];
            #pragma unroll
            for (int i = 0; i < 4; ++i)
                xacc[u] += fmaxf(acc[i][u] + bias, 0.0f);
        }
    }

    // ---- deterministic staged reduction of xacc over the 16 m-rows ----
    __syncthreads();
    float* sRed = slotE;  // 16 x 128
    #pragma unroll
    for (int u = 0; u < 8; ++u) sRed[tm * 128 + tn * 8 + u] = xacc[u];
    __syncthreads();
    if (tid < 128) {
        float s = 0.0f;
        #pragma unroll
        for (int r = 0; r < 16; ++r) s += sRed[r * 128 + tid];
        if (tid < 100) sX[tid] = s;
    } else if (tid < 192) {
        int d = tid - 128;
        sX[100 + d] = user_emb[(size_t)sI[35] * 64 + d];
    }
    __syncthreads();

    // ---- out[b][t] = b2[item] + W2[item] . sX  (one warp per t) ----
    int w = tid >> 5, lane = tid & 31;
    if (w < 3) {
        int it = sI[32 + w];
        const float* w2p = W2 + (size_t)it * 164;
        float s = 0.0f;
        for (int j = lane; j < 164; j += 32) s = fmaf(w2p[j], sX[j], s);
        #pragma unroll
        for (int off = 16; off; off >>= 1)
            s += __shfl_down_sync(0xffffffffu, s, off);
        if (lane == 0) out[b * 3 + w] = b2[it] + s;
    }
}

extern "C" void kernel_launch(void* const* d_in, const int* in_sizes, int n_in,
                              void* d_out, int out_size) {
    (void)in_sizes; (void)n_in; (void)out_size;
    cudaFuncSetAttribute(cosrec_kernel,
                         cudaFuncAttributeMaxDynamicSharedMemorySize,
                         (int)SMEM_BYTES);
    cosrec_kernel<<<512, THREADS, SMEM_BYTES>>>(
        (const int*)d_in[0],    // seq_var
        (const int*)d_in[1],    // user_var
        (const int*)d_in[2],    // item_var
        (const float*)d_in[3],  // item_emb
        (const float*)d_in[4],  // user_emb
        (const float*)d_in[5],  // W2
        (const float*)d_in[6],  // b2
        (const float*)d_in[7],  // W1
        (const float*)d_in[8],  // b1
        (const float*)d_in[9],  // Wf2
        (const float*)d_in[10], // bf2
        (float*)d_out);
}

// round 2
// speedup vs baseline: 1.2845x; 1.2845x over previous
#include <cuda_runtime.h>

// CosRec fused kernel — fp32, one CTA per batch row, h1 computed on the fly.
// Dominant work per CTA: (1024 x 100) @ (100 x 100) GEMM with fused
// relu(A[c]+B[a]) operand construction and relu+colsum epilogue.

#define THREADS 256
// XOR swizzle on g index of transposed Wf2 tile (float4 granularity).
#define SWZ(g, f) ((g) ^ (((f) & 7) << 2))

// Shared layout (floats):
//   sWt   [100][128]  Wf2^T (f-major, g zero-padded to 128)   12800
//   sAf   [100][32]   A + b1, f-major                          3200
//   sBf   [100][32]   Bm, f-major                              3200
//   slotU [6400]      W1 k-chunk staging (prologue only)       6400
//   slotE [2112]      E^T (64x33) / xacc reduction (16x128)    2112
//   sbf2  [128]       bf2 zero-padded                           128
//   sX    [164]       [x(100) | uemb(64)]                       164
//   sI    [36] ints
static const int SMEM_FLOATS = 12800 + 3200 + 3200 + 6400 + 2112 + 128 + 164;
static const size_t SMEM_BYTES = (size_t)SMEM_FLOATS * 4 + 36 * 4;

__global__ __launch_bounds__(THREADS, 2)
void cosrec_kernel(
    const int*   __restrict__ seq_var,   // [512*32]
    const int*   __restrict__ user_var,  // [512]
    const int*   __restrict__ item_var,  // [512*3]
    const float* __restrict__ item_emb,  // [100000*64]
    const float* __restrict__ user_emb,  // [100000*64]
    const float* __restrict__ W2,        // [100000*164]
    const float* __restrict__ b2,        // [100000]
    const float* __restrict__ W1,        // [100*128]
    const float* __restrict__ b1,        // [100]
    const float* __restrict__ Wf2,       // [100*100]
    const float* __restrict__ bf2,       // [100]
    float*       __restrict__ out)       // [512*3]
{
    extern __shared__ float smem[];
    float* sWt   = smem;              // 12800
    float* sAf   = sWt + 12800;       // 3200
    float* sBf   = sAf + 3200;        // 3200
    float* slotU = sBf + 3200;        // 6400
    float* slotE = slotU + 6400;      // 2112
    float* sbf2  = slotE + 2112;      // 128
    float* sX    = sbf2 + 128;        // 164
    int*   sI    = (int*)(sX + 164);  // 36 ints

    const int b   = blockIdx.x;
    const int tid = threadIdx.x;

    // ---- indices + small vectors ----
    if (tid < 32)                 sI[tid] = seq_var[b * 32 + tid];
    else if (tid < 35)            sI[tid] = item_var[b * 3 + (tid - 32)];
    else if (tid == 35)           sI[35]  = user_var[b];
    if (tid < 128)                sbf2[tid] = (tid < 100) ? bf2[tid] : 0.0f;
    for (int i = tid; i < 12800; i += THREADS) sWt[i] = 0.0f;  // zero incl. pad
    __syncthreads();

    // ---- gather embeddings: sEt[d*33 + l] ----
    float* sEt = slotE;
    for (int idx = tid; idx < 2048; idx += THREADS) {
        int l = idx >> 6, d = idx & 63;
        sEt[d * 33 + l] = item_emb[(size_t)sI[l] * 64 + d];
    }
    // ---- Wf2 -> transposed + swizzled shared tile ----
    for (int idx = tid; idx < 10000; idx += THREADS) {
        int g = idx / 100, f = idx - g * 100;
        sWt[f * 128 + SWZ(g, f)] = Wf2[idx];
    }
    __syncthreads();

    // ---- A = E@Wa^T + b1, Bm = E@Wb^T (W1 staged in two 32-k chunks) ----
    float* sW1c = slotU;  // [100][64]: cols 0..31 Wa chunk, 32..63 Wb chunk
    for (int c = 0; c < 2; ++c) {
        for (int idx = tid; idx < 6400; idx += THREADS) {
            int f = idx >> 6, jj = idx & 63;
            int half = jj >> 5, j = jj & 31;
            sW1c[idx] = W1[f * 128 + half * 64 + c * 32 + j];
        }
        __syncthreads();
        for (int idx = tid; idx < 3200; idx += THREADS) {
            int f = idx >> 5, l = idx & 31;
            float accA = 0.0f, accB = 0.0f;
            #pragma unroll
            for (int j = 0; j < 32; ++j) {
                float e = sEt[(c * 32 + j) * 33 + l];
                accA = fmaf(e, sW1c[f * 64 + j],      accA);
                accB = fmaf(e, sW1c[f * 64 + 32 + j], accB);
            }
            if (c == 0) { sAf[idx] = accA;          sBf[idx] = accB; }
            else        { sAf[idx] += accA + b1[f]; sBf[idx] += accB; }
        }
        __syncthreads();
    }
    // sAf/sBf/sWt now read-only; no further syncs in the mainloop.

    // ---- main GEMM: h1 built in registers, 8(pairs) x 8(g) per thread ----
    // pair p = a*32 + c; h1[p][f] = relu(sAf[f][c] + sBf[f][a])
    const int tn    = tid & 15;        // g octet: g = tn*8 + u
    const int to    = tid >> 4;        // pair octet (0..15)
    const int a_loc = to >> 2;         // a offset within 128-pair supertile
    const int c0    = (to & 3) * 8;    // c base (8 contiguous c per thread)

    float xacc[8];
    #pragma unroll
    for (int u = 0; u < 8; ++u) xacc[u] = 0.0f;

    for (int mt = 0; mt < 8; ++mt) {   // 8 supertiles x 128 pairs = 1024
        const int a = mt * 4 + a_loc;

        float acc[8][8];
        #pragma unroll
        for (int i = 0; i < 8; ++i)
            #pragma unroll
            for (int u = 0; u < 8; ++u) acc[i][u] = 0.0f;

        #pragma unroll 2
        for (int f = 0; f < 100; ++f) {
            float4 a0 = *(const float4*)(sAf + f * 32 + c0);
            float4 a1 = *(const float4*)(sAf + f * 32 + c0 + 4);
            float  bs = sBf[f * 32 + a];
            const float* wp = sWt + f * 128;
            float4 w0 = *(const float4*)(wp + SWZ(tn * 8,     f));
            float4 w1 = *(const float4*)(wp + SWZ(tn * 8 + 4, f));

            float h[8];
            h[0] = fmaxf(a0.x + bs, 0.0f);
            h[1] = fmaxf(a0.y + bs, 0.0f);
            h[2] = fmaxf(a0.z + bs, 0.0f);
            h[3] = fmaxf(a0.w + bs, 0.0f);
            h[4] = fmaxf(a1.x + bs, 0.0f);
            h[5] = fmaxf(a1.y + bs, 0.0f);
            h[6] = fmaxf(a1.z + bs, 0.0f);
            h[7] = fmaxf(a1.w + bs, 0.0f);
            float w[8] = {w0.x, w0.y, w0.z, w0.w, w1.x, w1.y, w1.z, w1.w};

            #pragma unroll
            for (int i = 0; i < 8; ++i)
                #pragma unroll
                for (int u = 0; u < 8; ++u)
                    acc[i][u] = fmaf(h[i], w[u], acc[i][u]);
        }
        // bias + relu + accumulate into per-thread x (g-pad contributes 0)
        #pragma unroll
        for (int u = 0; u < 8; ++u) {
            float bias = sbf2[tn * 8 + u];
            #pragma unroll
            for (int i = 0; i < 8; ++i)
                xacc[u] += fmaxf(acc[i][u] + bias, 0.0f);
        }
    }

    // ---- deterministic staged reduction over the 16 pair-octets ----
    __syncthreads();                   // slotE handoff (E^T dead)
    float* sRed = slotE;               // 16 x 128
    #pragma unroll
    for (int u = 0; u < 8; ++u) sRed[to * 128 + tn * 8 + u] = xacc[u];
    __syncthreads();
    if (tid < 128) {
        float s = 0.0f;
        #pragma unroll
        for (int r = 0; r < 16; ++r) s += sRed[r * 128 + tid];
        if (tid < 100) sX[tid] = s;
    } else if (tid < 192) {
        int d = tid - 128;
        sX[100 + d] = user_emb[(size_t)sI[35] * 64 + d];
    }
    __syncthreads();

    // ---- out[b][t] = b2[item] + W2[item] . sX  (one warp per t) ----
    int w = tid >> 5, lane = tid & 31;
    if (w < 3) {
        int it = sI[32 + w];
        const float* w2p = W2 + (size_t)it * 164;
        float s = 0.0f;
        for (int j = lane; j < 164; j += 32) s = fmaf(w2p[j], sX[j], s);
        #pragma unroll
        for (int off = 16; off; off >>= 1)
            s += __shfl_down_sync(0xffffffffu, s, off);
        if (lane == 0) out[b * 3 + w] = b2[it] + s;
    }
}

extern "C" void kernel_launch(void* const* d_in, const int* in_sizes, int n_in,
                              void* d_out, int out_size) {
    (void)in_sizes; (void)n_in; (void)out_size;
    cudaFuncSetAttribute(cosrec_kernel,
                         cudaFuncAttributeMaxDynamicSharedMemorySize,
                         (int)SMEM_BYTES);
    cosrec_kernel<<<512, THREADS, SMEM_BYTES>>>(
        (const int*)d_in[0],    // seq_var
        (const int*)d_in[1],    // user_var
        (const int*)d_in[2],    // item_var
        (const float*)d_in[3],  // item_emb
        (const float*)d_in[4],  // user_emb
        (const float*)d_in[5],  // W2
        (const float*)d_in[6],  // b2
        (const float*)d_in[7],  // W1
        (const float*)d_in[8],  // b1
        (const float*)d_in[9],  // Wf2
        (const float*)d_in[10], // bf2
        (float*)d_out);
}

// round 3
// speedup vs baseline: 1.4845x; 1.1557x over previous
#include <cuda_runtime.h>

// CosRec fused kernel — fp32, one CTA per batch row, h1 built in registers.
// Round 3: no register spills (launch_bounds(256,1) -> 255-reg budget),
// swizzle-free padded Wf2 tile (stride 132), pointer-increment mainloop.

#define THREADS 256
#define WSTRIDE 132   // Wf2^T row stride in floats (128 used + 4 pad, f4-aligned)

// Shared layout (floats):
//   sWt   [100][132]  Wf2^T (f-major, g zero-padded to 128, stride 132) 13200
//   sAf   [100][32]   A + b1, f-major                                    3200
//   sBf   [100][32]   Bm, f-major                                        3200
//   slotU [6400]      W1 k-chunk staging (prologue only)                 6400
//   slotE [2112]      E^T (64x33) / xacc reduction (16x128)              2112
//   sbf2  [128]       bf2 zero-padded                                     128
//   sX    [164]       [x(100) | uemb(64)]                                 164
//   sI    [36] ints
static const int SMEM_FLOATS = 13200 + 3200 + 3200 + 6400 + 2112 + 128 + 164;
static const size_t SMEM_BYTES = (size_t)SMEM_FLOATS * 4 + 36 * 4;

__global__ __launch_bounds__(THREADS, 1)
void cosrec_kernel(
    const int*   __restrict__ seq_var,   // [512*32]
    const int*   __restrict__ user_var,  // [512]
    const int*   __restrict__ item_var,  // [512*3]
    const float* __restrict__ item_emb,  // [100000*64]
    const float* __restrict__ user_emb,  // [100000*64]
    const float* __restrict__ W2,        // [100000*164]
    const float* __restrict__ b2,        // [100000]
    const float* __restrict__ W1,        // [100*128]
    const float* __restrict__ b1,        // [100]
    const float* __restrict__ Wf2,       // [100*100]
    const float* __restrict__ bf2,       // [100]
    float*       __restrict__ out)       // [512*3]
{
    extern __shared__ float smem[];
    float* sWt   = smem;               // 13200
    float* sAf   = sWt + 13200;        // 3200
    float* sBf   = sAf + 3200;         // 3200
    float* slotU = sBf + 3200;         // 6400
    float* slotE = slotU + 6400;       // 2112
    float* sbf2  = slotE + 2112;       // 128
    float* sX    = sbf2 + 128;         // 164
    int*   sI    = (int*)(sX + 164);   // 36 ints

    const int b   = blockIdx.x;
    const int tid = threadIdx.x;

    // ---- indices + small vectors ----
    if (tid < 32)                 sI[tid] = seq_var[b * 32 + tid];
    else if (tid < 35)            sI[tid] = item_var[b * 3 + (tid - 32)];
    else if (tid == 35)           sI[35]  = user_var[b];
    if (tid < 128)                sbf2[tid] = (tid < 100) ? bf2[tid] : 0.0f;
    for (int i = tid; i < 13200; i += THREADS) sWt[i] = 0.0f;  // zero incl. pad
    __syncthreads();

    // ---- gather embeddings: sEt[d*33 + l] ----
    float* sEt = slotE;
    for (int idx = tid; idx < 2048; idx += THREADS) {
        int l = idx >> 6, d = idx & 63;
        sEt[d * 33 + l] = item_emb[(size_t)sI[l] * 64 + d];
    }
    // ---- Wf2 -> transposed shared tile (one-time; write conflicts OK) ----
    for (int idx = tid; idx < 10000; idx += THREADS) {
        int g = idx / 100, f = idx - g * 100;
        sWt[f * WSTRIDE + g] = Wf2[idx];
    }
    __syncthreads();

    // ---- A = E@Wa^T + b1, Bm = E@Wb^T (W1 staged in two 32-k chunks) ----
    float* sW1c = slotU;  // [100][64]: cols 0..31 Wa chunk, 32..63 Wb chunk
    for (int c = 0; c < 2; ++c) {
        for (int idx = tid; idx < 6400; idx += THREADS) {
            int f = idx >> 6, jj = idx & 63;
            int half = jj >> 5, j = jj & 31;
            sW1c[idx] = W1[f * 128 + half * 64 + c * 32 + j];
        }
        __syncthreads();
        for (int idx = tid; idx < 3200; idx += THREADS) {
            int f = idx >> 5, l = idx & 31;
            float accA = 0.0f, accB = 0.0f;
            #pragma unroll
            for (int j = 0; j < 32; ++j) {
                float e = sEt[(c * 32 + j) * 33 + l];
                accA = fmaf(e, sW1c[f * 64 + j],      accA);
                accB = fmaf(e, sW1c[f * 64 + 32 + j], accB);
            }
            if (c == 0) { sAf[idx] = accA;          sBf[idx] = accB; }
            else        { sAf[idx] += accA + b1[f]; sBf[idx] += accB; }
        }
        __syncthreads();
    }
    // sAf/sBf/sWt now read-only; no further syncs in the mainloop.

    // ---- main GEMM: h1 built in registers, 8(pairs) x 8(g) per thread ----
    // pair p = a*32 + c; h1[p][f] = relu(sAf[f][c] + sBf[f][a])
    const int tn    = tid & 15;        // g octet: g = tn*8 + u
    const int to    = tid >> 4;        // pair octet (0..15)
    const int a_loc = to >> 2;         // a offset within 128-pair supertile
    const int c0    = (to & 3) * 8;    // c base (8 contiguous c per thread)

    float xacc[8];
    #pragma unroll
    for (int u = 0; u < 8; ++u) xacc[u] = 0.0f;

    for (int mt = 0; mt < 8; ++mt) {   // 8 supertiles x 128 pairs = 1024
        const int a = mt * 4 + a_loc;

        float acc[8][8];
        #pragma unroll
        for (int i = 0; i < 8; ++i)
            #pragma unroll
            for (int u = 0; u < 8; ++u) acc[i][u] = 0.0f;

        const float* pA = sAf + c0;
        const float* pB = sBf + a;
        const float* pW = sWt + tn * 8;

        #pragma unroll 2
        for (int f = 0; f < 100; ++f) {
            float4 a0 = *(const float4*)(pA);
            float4 a1 = *(const float4*)(pA + 4);
            float  bs = *pB;
            float4 w0 = *(const float4*)(pW);
            float4 w1 = *(const float4*)(pW + 4);
            pA += 32; pB += 32; pW += WSTRIDE;

            float h[8];
            h[0] = fmaxf(a0.x + bs, 0.0f);
            h[1] = fmaxf(a0.y + bs, 0.0f);
            h[2] = fmaxf(a0.z + bs, 0.0f);
            h[3] = fmaxf(a0.w + bs, 0.0f);
            h[4] = fmaxf(a1.x + bs, 0.0f);
            h[5] = fmaxf(a1.y + bs, 0.0f);
            h[6] = fmaxf(a1.z + bs, 0.0f);
            h[7] = fmaxf(a1.w + bs, 0.0f);
            float w[8] = {w0.x, w0.y, w0.z, w0.w, w1.x, w1.y, w1.z, w1.w};

            #pragma unroll
            for (int i = 0; i < 8; ++i)
                #pragma unroll
                for (int u = 0; u < 8; ++u)
                    acc[i][u] = fmaf(h[i], w[u], acc[i][u]);
        }
        // bias + relu + accumulate into per-thread x (g-pad contributes 0)
        #pragma unroll
        for (int u = 0; u < 8; ++u) {
            float bias = sbf2[tn * 8 + u];
            #pragma unroll
            for (int i = 0; i < 8; ++i)
                xacc[u] += fmaxf(acc[i][u] + bias, 0.0f);
        }
    }

    // ---- deterministic staged reduction over the 16 pair-octets ----
    __syncthreads();                   // slotE handoff (E^T dead)
    float* sRed = slotE;               // 16 x 128
    #pragma unroll
    for (int u = 0; u < 8; ++u) sRed[to * 128 + tn * 8 + u] = xacc[u];
    __syncthreads();
    if (tid < 128) {
        float s = 0.0f;
        #pragma unroll
        for (int r = 0; r < 16; ++r) s += sRed[r * 128 + tid];
        if (tid < 100) sX[tid] = s;
    } else if (tid < 192) {
        int d = tid - 128;
        sX[100 + d] = user_emb[(size_t)sI[35] * 64 + d];
    }
    __syncthreads();

    // ---- out[b][t] = b2[item] + W2[item] . sX  (one warp per t) ----
    int w = tid >> 5, lane = tid & 31;
    if (w < 3) {
        int it = sI[32 + w];
        const float* w2p = W2 + (size_t)it * 164;
        float s = 0.0f;
        for (int j = lane; j < 164; j += 32) s = fmaf(w2p[j], sX[j], s);
        #pragma unroll
        for (int off = 16; off; off >>= 1)
            s += __shfl_down_sync(0xffffffffu, s, off);
        if (lane == 0) out[b * 3 + w] = b2[it] + s;
    }
}

extern "C" void kernel_launch(void* const* d_in, const int* in_sizes, int n_in,
                              void* d_out, int out_size) {
    (void)in_sizes; (void)n_in; (void)out_size;
    cudaFuncSetAttribute(cosrec_kernel,
                         cudaFuncAttributeMaxDynamicSharedMemorySize,
                         (int)SMEM_BYTES);
    cosrec_kernel<<<512, THREADS, SMEM_BYTES>>>(
        (const int*)d_in[0],    // seq_var
        (const int*)d_in[1],    // user_var
        (const int*)d_in[2],    // item_var
        (const float*)d_in[3],  // item_emb
        (const float*)d_in[4],  // user_emb
        (const float*)d_in[5],  // W2
        (const float*)d_in[6],  // b2
        (const float*)d_in[7],  // W1
        (const float*)d_in[8],  // b1
        (const float*)d_in[9],  // Wf2
        (const float*)d_in[10], // bf2
        (float*)d_out);
}

// round 5
// speedup vs baseline: 5.4065x; 3.6418x over previous
#include <cuda_runtime.h>
#include <cuda_fp16.h>
#include <stdint.h>

// CosRec fused kernel — fp16 mma.sync (HMMA) version.
// Per CTA (batch row): prologue computes A,B in fp32, packs half2 operand
// tables (k-padded to 112 with bias column k=100) and Wf2 B-fragments in
// mma.sync fragment order; mainloop: 8 warps x 8 m-tiles, A-fragments built
// in registers (relu(A[c]+B[a])), 728 HMMA/warp, relu+colsum in registers.
// No __syncthreads in the mainloop.

#define THREADS 256

// ---- shared memory byte offsets ----
#define OFF_SI    0        // 36 ints
#define OFF_SX    160      // 164 floats (ends 816)
#define OFF_A2    1024     // uint32 A-table [56 k2][32 c]  = 7168 B
#define OFF_B2    8192     // uint32 B-table [56 k2][32 a]  = 7168 B
#define OFF_X     15360    // region X: W1 staging (25600 B) then B-frags (23296 B)
#define OFF_AF    40960    // fp32 A [100 f][32 c] = 12800 B
#define OFF_BF    53760    // fp32 B [100 f][32 a] = 12800 B
#define OFF_ET    66560    // fp32 E^T [64][33] = 8448 B ; later sRedW[8][104]
#define SMEM_TOTAL 75008

__device__ __forceinline__ void mma16816(float* d, uint32_t a0, uint32_t a1,
                                         uint32_t a2, uint32_t a3,
                                         uint32_t b0, uint32_t b1) {
    asm volatile(
        "mma.sync.aligned.m16n8k16.row.col.f32.f16.f16.f32 "
        "{%0,%1,%2,%3}, {%4,%5,%6,%7}, {%8,%9}, {%0,%1,%2,%3};"
        : "+f"(d[0]), "+f"(d[1]), "+f"(d[2]), "+f"(d[3])
        : "r"(a0), "r"(a1), "r"(a2), "r"(a3), "r"(b0), "r"(b1));
}

__device__ __forceinline__ uint32_t hbuild(uint32_t a, uint32_t b) {
    __half2 av = *reinterpret_cast<__half2*>(&a);
    __half2 bv = *reinterpret_cast<__half2*>(&b);
    __half2 r  = __hmax2(__hadd2(av, bv), __float2half2_rn(0.0f));
    return *reinterpret_cast<uint32_t*>(&r);
}

__global__ __launch_bounds__(THREADS, 1)
void cosrec_kernel(
    const int*   __restrict__ seq_var,   // [512*32]
    const int*   __restrict__ user_var,  // [512]
    const int*   __restrict__ item_var,  // [512*3]
    const float* __restrict__ item_emb,  // [100000*64]
    const float* __restrict__ user_emb,  // [100000*64]
    const float* __restrict__ W2,        // [100000*164]
    const float* __restrict__ b2,        // [100000]
    const float* __restrict__ W1,        // [100*128]
    const float* __restrict__ b1,        // [100]
    const float* __restrict__ Wf2,       // [100*100]
    const float* __restrict__ bf2,       // [100]
    float*       __restrict__ out)       // [512*3]
{
    extern __shared__ char smem[];
    int*      sI    = (int*)(smem + OFF_SI);
    float*    sX    = (float*)(smem + OFF_SX);
    uint32_t* uA2   = (uint32_t*)(smem + OFF_A2);
    uint32_t* uB2   = (uint32_t*)(smem + OFF_B2);
    float*    sAf   = (float*)(smem + OFF_AF);
    float*    sBf   = (float*)(smem + OFF_BF);
    float*    sEt   = (float*)(smem + OFF_ET);

    const int b    = blockIdx.x;
    const int tid  = threadIdx.x;
    const int wid  = tid >> 5;
    const int lane = tid & 31;

    // ---- phase 0: indices ----
    if (tid < 32)       sI[tid] = seq_var[b * 32 + tid];
    else if (tid < 35)  sI[tid] = item_var[b * 3 + (tid - 32)];
    else if (tid == 35) sI[35]  = user_var[b];
    __syncthreads();

    // ---- phase 1: gather E^T ----
    for (int idx = tid; idx < 2048; idx += THREADS) {
        int l = idx >> 6, d = idx & 63;
        sEt[d * 33 + l] = item_emb[(size_t)sI[l] * 64 + d];
    }

    // ---- phase 2: A = E@Wa^T + b1, B = E@Wb^T (W1 staged in region X) ----
    float* sW1c = (float*)(smem + OFF_X);  // [100][64]
    for (int c = 0; c < 2; ++c) {
        __syncthreads();
        for (int idx = tid; idx < 6400; idx += THREADS) {
            int f = idx >> 6, jj = idx & 63;
            int half_ = jj >> 5, j = jj & 31;
            sW1c[idx] = W1[f * 128 + half_ * 64 + c * 32 + j];
        }
        __syncthreads();
        for (int idx = tid; idx < 3200; idx += THREADS) {
            int f = idx >> 5, l = idx & 31;
            float accA = 0.0f, accB = 0.0f;
            #pragma unroll
            for (int j = 0; j < 32; ++j) {
                float e = sEt[(c * 32 + j) * 33 + l];
                accA = fmaf(e, sW1c[f * 64 + j],      accA);
                accB = fmaf(e, sW1c[f * 64 + 32 + j], accB);
            }
            if (c == 0) { sAf[idx] = accA;          sBf[idx] = accB; }
            else        { sAf[idx] += accA + b1[f]; sBf[idx] += accB; }
        }
    }
    __syncthreads();

    // ---- phase 3a: pack half2 tables, k2 in [0,56) (k padded to 112) ----
    // k2 < 50: real (k=2*k2, 2*k2+1). k2 == 50: bias column (h==1 exactly:
    // A=(1,0), B=(0,0)). k2 > 50: zero padding.
    for (int idx = tid; idx < 56 * 32; idx += THREADS) {
        int kk = idx >> 5, c = idx & 31;
        __half2 va, vb;
        if (kk < 50) {
            va = __floats2half2_rn(sAf[(2 * kk) * 32 + c], sAf[(2 * kk + 1) * 32 + c]);
            vb = __floats2half2_rn(sBf[(2 * kk) * 32 + c], sBf[(2 * kk + 1) * 32 + c]);
        } else if (kk == 50) {
            va = __floats2half2_rn(1.0f, 0.0f);
            vb = __float2half2_rn(0.0f);
        } else {
            va = __float2half2_rn(0.0f);
            vb = __float2half2_rn(0.0f);
        }
        uA2[idx] = *reinterpret_cast<uint32_t*>(&va);
        uB2[idx] = *reinterpret_cast<uint32_t*>(&vb);
    }

    // ---- phase 3b: pack Wf2 B-fragments (fragment order, col-major B) ----
    // W(n,k): n<100 & k<100 -> Wf2[n][k]; n<100 & k==100 -> bf2[n]; else 0.
    // frag (nt, ks), lane ln: n = nt*8 + ln/4, k0 = ks*16 + (ln%4)*2;
    // b0 = {W(n,k0), W(n,k0+1)}, b1 = {W(n,k0+8), W(n,k0+9)}.
    uint2* bfragW = (uint2*)(smem + OFF_X);
    for (int idx = tid; idx < 13 * 7 * 32; idx += THREADS) {
        int nt  = idx / 224;
        int rem = idx - nt * 224;
        int ks  = rem >> 5, ln = rem & 31;
        int n   = nt * 8 + (ln >> 2);
        int k0  = ks * 16 + (ln & 3) * 2;
        float w0, w1, w2v, w3v;
        if (n < 100) {
            const float* wr = Wf2 + n * 100;
            w0  = (k0     < 100) ? wr[k0]     : ((k0     == 100) ? bf2[n] : 0.0f);
            w1  = (k0 + 1 < 100) ? wr[k0 + 1] : ((k0 + 1 == 100) ? bf2[n] : 0.0f);
            w2v = (k0 + 8 < 100) ? wr[k0 + 8] : ((k0 + 8 == 100) ? bf2[n] : 0.0f);
            w3v = (k0 + 9 < 100) ? wr[k0 + 9] : ((k0 + 9 == 100) ? bf2[n] : 0.0f);
        } else {
            w0 = w1 = w2v = w3v = 0.0f;
        }
        __half2 lo = __floats2half2_rn(w0, w1);
        __half2 hi = __floats2half2_rn(w2v, w3v);
        uint2 val;
        val.x = *reinterpret_cast<uint32_t*>(&lo);
        val.y = *reinterpret_cast<uint32_t*>(&hi);
        bfragW[idx] = val;
    }
    __syncthreads();

    // ---- mainloop: 8 m-tiles of 16 pairs per warp; no CTA syncs ----
    const int gid = lane >> 2;   // row group 0..7
    const int tig = lane & 3;    // k/col group 0..3

    float xacc[26];
    #pragma unroll
    for (int j = 0; j < 26; ++j) xacc[j] = 0.0f;

    for (int mt = 0; mt < 8; ++mt) {
        // pair p0 = wid*128 + mt*16 + gid, p1 = p0 + 8; same a-block, c split.
        const int p0 = wid * 128 + mt * 16 + gid;
        const int aI = p0 >> 5;
        const int cA = p0 & 31;
        const int cB = cA + 8;

        float acc[13][4];
        #pragma unroll
        for (int nt = 0; nt < 13; ++nt)
            #pragma unroll
            for (int e = 0; e < 4; ++e) acc[nt][e] = 0.0f;

        #pragma unroll
        for (int ks = 0; ks < 7; ++ks) {
            const int k2a = ks * 8 + tig;
            const int k2b = k2a + 4;
            uint32_t Ba = uB2[k2a * 32 + aI];
            uint32_t Bb = uB2[k2b * 32 + aI];
            uint32_t a0 = hbuild(uA2[k2a * 32 + cA], Ba);
            uint32_t a1 = hbuild(uA2[k2a * 32 + cB], Ba);
            uint32_t a2 = hbuild(uA2[k2b * 32 + cA], Bb);
            uint32_t a3 = hbuild(uA2[k2b * 32 + cB], Bb);
            #pragma unroll
            for (int nt = 0; nt < 13; ++nt) {
                uint2 bb = bfragW[(nt * 7 + ks) * 32 + lane];
                mma16816(acc[nt], a0, a1, a2, a3, bb.x, bb.y);
            }
        }
        // relu + colsum into registers (per-element relu, rows p0 and p1)
        #pragma unroll
        for (int nt = 0; nt < 13; ++nt) {
            xacc[nt * 2]     += fmaxf(acc[nt][0], 0.0f) + fmaxf(acc[nt][2], 0.0f);
            xacc[nt * 2 + 1] += fmaxf(acc[nt][1], 0.0f) + fmaxf(acc[nt][3], 0.0f);
        }
    }

    // ---- reduction: shfl over row-groups, then fixed-order over warps ----
    #pragma unroll
    for (int j = 0; j < 26; ++j) {
        float s = xacc[j];
        s += __shfl_down_sync(0xffffffffu, s, 16);
        s += __shfl_down_sync(0xffffffffu, s, 8);
        s += __shfl_down_sync(0xffffffffu, s, 4);
        xacc[j] = s;
    }
    float* sRedW = (float*)(smem + OFF_ET);  // [8][104], overlays dead E^T
    if (lane < 4) {
        #pragma unroll
        for (int nt = 0; nt < 13; ++nt) {
            int n0 = nt * 8 + lane * 2;      // lane == tig here
            sRedW[wid * 104 + n0]     = xacc[nt * 2];
            sRedW[wid * 104 + n0 + 1] = xacc[nt * 2 + 1];
        }
    }
    __syncthreads();
    if (tid < 100) {
        float s = 0.0f;
        #pragma unroll
        for (int w = 0; w < 8; ++w) s += sRedW[w * 104 + tid];
        sX[tid] = s;
    } else if (tid >= 128 && tid < 192) {
        int d = tid - 128;
        sX[100 + d] = user_emb[(size_t)sI[35] * 64 + d];
    }
    __syncthreads();

    // ---- out[b][t] = b2[item] + W2[item] . sX (one warp per t) ----
    if (wid < 3) {
        int it = sI[32 + wid];
        const float* w2p = W2 + (size_t)it * 164;
        float s = 0.0f;
        for (int j = lane; j < 164; j += 32) s = fmaf(w2p[j], sX[j], s);
        #pragma unroll
        for (int off = 16; off; off >>= 1)
            s += __shfl_down_sync(0xffffffffu, s, off);
        if (lane == 0) out[b * 3 + wid] = b2[it] + s;
    }
}

extern "C" void kernel_launch(void* const* d_in, const int* in_sizes, int n_in,
                              void* d_out, int out_size) {
    (void)in_sizes; (void)n_in; (void)out_size;
    cudaFuncSetAttribute(cosrec_kernel,
                         cudaFuncAttributeMaxDynamicSharedMemorySize, SMEM_TOTAL);
    cosrec_kernel<<<512, THREADS, SMEM_TOTAL>>>(
        (const int*)d_in[0],    // seq_var
        (const int*)d_in[1],    // user_var
        (const int*)d_in[2],    // item_var
        (const float*)d_in[3],  // item_emb
        (const float*)d_in[4],  // user_emb
        (const float*)d_in[5],  // W2
        (const float*)d_in[6],  // b2
        (const float*)d_in[7],  // W1
        (const float*)d_in[8],  // b1
        (const float*)d_in[9],  // Wf2
        (const float*)d_in[10], // bf2
        (float*)d_out);
}